// round 6
// baseline (speedup 1.0000x reference)
#include <cuda_runtime.h>
#include <math.h>

// Problem constants
#define T_STEPS 100
#define BATCH   64
#define ISZ     256
#define HSZ     512
#define G4      2048   // 4H
#define G3      1536   // 3H
#define NCHUNK  4
#define CLEN    25

// Output layout: outputs[T,B,H], cx[B,H], ev_ih[B,3H,I], ev_hh[B,3H,H], ev_b[B,3H,1]
#define OUT_CX   (T_STEPS*BATCH*HSZ)
#define OUT_EVIH (OUT_CX + BATCH*HSZ)
#define OUT_EVHH (OUT_EVIH + BATCH*G3*ISZ)
#define OUT_EVB  (OUT_EVHH + BATCH*G3*HSZ)

typedef unsigned long long ull;

// Device scratch
__device__ float g_bias[G4];
__device__ float g_Gin[T_STEPS*BATCH*G4];
__device__ float g_hh[T_STEPS*BATCH*HSZ];
__device__ float g_d[T_STEPS*BATCH*G3];
__device__ float g_f[T_STEPS*BATCH*HSZ];
__device__ float g_hbuf[2][HSZ*BATCH];             // k-major: [h][b]
__device__ float g_Fc[NCHUNK][BATCH*HSZ];
__device__ float g_ps[NCHUNK][BATCH*G3];
__device__ unsigned g_flags[128];

// ---- f32x2 packed helpers -------------------------------------------------
__device__ __forceinline__ ull ffma2(ull a, ull b, ull c) {
    ull d; asm("fma.rn.f32x2 %0, %1, %2, %3;" : "=l"(d) : "l"(a), "l"(b), "l"(c)); return d;
}
__device__ __forceinline__ ull fadd2(ull a, ull b) {
    ull d; asm("add.rn.f32x2 %0, %1, %2;" : "=l"(d) : "l"(a), "l"(b)); return d;
}
__device__ __forceinline__ ull fdup(float x) {
    ull d; asm("mov.b64 %0, {%1, %1};" : "=l"(d) : "f"(x)); return d;
}
__device__ __forceinline__ float2 unpk(ull v) {
    float2 r; asm("mov.b64 {%0, %1}, %2;" : "=f"(r.x), "=f"(r.y) : "l"(v)); return r;
}

// ---------------------------------------------------------------------------
__global__ void prep_kernel(const float* __restrict__ bih, const float* __restrict__ bhh,
                            const float* __restrict__ h0) {
    int gid = blockIdx.x * blockDim.x + threadIdx.x;
    if (gid < 128) g_flags[gid] = 0u;
    if (gid < G4) g_bias[gid] = bih[gid] + bhh[gid];
    if (gid < BATCH*HSZ) {
        int k = gid >> 6, b = gid & 63;
        g_hbuf[0][gid] = h0[b*HSZ + k];     // k-major
    }
}

__global__ void dummy_kernel() {}

// ---------------------------------------------------------------------------
// Gin[r][j] = sum_i X[r][i]*W_ih[j][i] + bias[j].  128x128 tile, 8x8/thread.
__global__ __launch_bounds__(256) void gin_kernel(const float* __restrict__ X,
                                                  const float* __restrict__ Wih) {
    __shared__ float As[32][136];
    __shared__ float Bs[32][136];
    const int j0 = blockIdx.x * 128;
    const int r0 = blockIdx.y * 128;
    const int tx = threadIdx.x & 15, ty = threadIdx.x >> 4;
    ull acc[8][4] = {};
    for (int k0 = 0; k0 < ISZ; k0 += 32) {
        for (int idx = threadIdx.x; idx < 128*8; idx += 256) {
            int rr = idx >> 3, kq = idx & 7;
            float4 v = *(const float4*)&X[(r0+rr)*ISZ + k0 + kq*4];
            As[kq*4+0][rr] = v.x; As[kq*4+1][rr] = v.y;
            As[kq*4+2][rr] = v.z; As[kq*4+3][rr] = v.w;
        }
        for (int idx = threadIdx.x; idx < 128*8; idx += 256) {
            int jj = idx >> 3, kq = idx & 7;
            float4 v = *(const float4*)&Wih[(j0+jj)*ISZ + k0 + kq*4];
            Bs[kq*4+0][jj] = v.x; Bs[kq*4+1][jj] = v.y;
            Bs[kq*4+2][jj] = v.z; Bs[kq*4+3][jj] = v.w;
        }
        __syncthreads();
        #pragma unroll
        for (int kk = 0; kk < 32; kk++) {
            float4 a0 = *(const float4*)&As[kk][ty*8];
            float4 a1 = *(const float4*)&As[kk][ty*8+4];
            ulonglong2 bv0 = *(const ulonglong2*)&Bs[kk][tx*8];
            ulonglong2 bv1 = *(const ulonglong2*)&Bs[kk][tx*8+4];
            ull ad[8];
            ad[0]=fdup(a0.x); ad[1]=fdup(a0.y); ad[2]=fdup(a0.z); ad[3]=fdup(a0.w);
            ad[4]=fdup(a1.x); ad[5]=fdup(a1.y); ad[6]=fdup(a1.z); ad[7]=fdup(a1.w);
            #pragma unroll
            for (int r = 0; r < 8; r++) {
                acc[r][0] = ffma2(ad[r], bv0.x, acc[r][0]);
                acc[r][1] = ffma2(ad[r], bv0.y, acc[r][1]);
                acc[r][2] = ffma2(ad[r], bv1.x, acc[r][2]);
                acc[r][3] = ffma2(ad[r], bv1.y, acc[r][3]);
            }
        }
        __syncthreads();
    }
    float4 b0 = *(const float4*)&g_bias[j0 + tx*8];
    float4 b1 = *(const float4*)&g_bias[j0 + tx*8 + 4];
    #pragma unroll
    for (int r = 0; r < 8; r++) {
        float2 p0 = unpk(acc[r][0]), p1 = unpk(acc[r][1]);
        float2 p2 = unpk(acc[r][2]), p3 = unpk(acc[r][3]);
        float* dst = &g_Gin[(r0+ty*8+r)*G4 + j0 + tx*8];
        *(float4*)dst       = make_float4(p0.x+b0.x, p0.y+b0.y, p1.x+b0.z, p1.y+b0.w);
        *(float4*)(dst + 4) = make_float4(p2.x+b1.x, p2.y+b1.y, p3.x+b1.z, p3.y+b1.w);
    }
}

// ---------------------------------------------------------------------------
// Persistent recurrence: 128 CTAs x 512 threads.
// CTA n: batch-half hb=n&1 (32 b), cell-group cg=n>>1 (8 cells -> 32 gate-cols).
#define NB_REC 128
#define RT     512
#define SROW   36

// smem float offsets
#define OFF_WS 0
#define OFF_HS (512*SROW)                 // 18432
#define OFF_PT (2*512*SROW)               // 36864 (ull: 16*513)
#define OFF_GB (OFF_PT + 16*513*2)        // 53280
#define OFF_CS (OFF_GB + 32*33)           // 54336
#define REC_SMEM_FLOATS (OFF_CS + 256)    // 54592
#define REC_SMEM_BYTES  (REC_SMEM_FLOATS*4)

// Flag-array grid barrier: 1 STG per CTA, warp 0 polls 128 flags (4/lane).
__device__ __forceinline__ void grid_sync_flags(int n, int t) {
    __syncthreads();
    if (threadIdx.x == 0) {
        __threadfence();
        *(volatile unsigned*)&g_flags[n] = (unsigned)(t + 1);
    }
    if (threadIdx.x < 32) {
        const unsigned target = (unsigned)(t + 1);
        bool ok;
        do {
            ok = (*(volatile unsigned*)&g_flags[threadIdx.x]       >= target)
              && (*(volatile unsigned*)&g_flags[threadIdx.x + 32]  >= target)
              && (*(volatile unsigned*)&g_flags[threadIdx.x + 64]  >= target)
              && (*(volatile unsigned*)&g_flags[threadIdx.x + 96]  >= target);
        } while (__ballot_sync(0xffffffffu, !ok));
        __threadfence();
    }
    __syncthreads();
}

__global__ __launch_bounds__(RT) void recur_kernel(const float* __restrict__ Whh,
                                                   const float* __restrict__ c0,
                                                   float* __restrict__ out) {
    extern __shared__ float sm[];
    float* ws = sm + OFF_WS;          // [512][SROW] ws[k][c]
    float* hs = sm + OFF_HS;          // [512][SROW] hs[k][b]
    ull*   pt = (ull*)(sm + OFF_PT);  // [16][513]
    float* gb = sm + OFF_GB;          // [32][33] final gates
    float* cs = sm + OFF_CS;          // [256]

    const int tid = threadIdx.x;
    const int n   = blockIdx.x;
    const int hb  = n & 1, cg = n >> 1;
    // GEMM mapping
    const int ks = tid >> 5, lane = tid & 31;
    const int cq = lane >> 2, bq = lane & 3;
    // reduce mapping
    const int r_l = tid & 31, r_i = tid >> 5;
    const int r_col = ((r_l >> 2) << 2) + (r_i >> 2);
    const int r_bp  = ((r_l & 3) << 2) + (r_i & 3);
    const int r_jg  = ((r_col >> 3) * HSZ) + cg*8 + (r_col & 7);
    // activation mapping (tid < 256)
    const int ab = tid >> 3, acc_ = tid & 7;
    const int ahg = cg*8 + acc_;
    const int abg = hb*32 + ab;

    // one-time: weights transposed ws[k][c], c-state
    for (int idx = tid; idx < 32*512; idx += RT) {
        int c = idx >> 9, k = idx & 511;
        int jg = ((c >> 3) * HSZ) + cg*8 + (c & 7);
        ws[k*SROW + c] = Whh[jg*HSZ + k];
    }
    if (tid < 256) cs[tid] = c0[abg*HSZ + ahg];
    float Facc = 1.f;
    __syncthreads();

    for (int t = 0; t < T_STEPS; t++) {
        const int cur = t & 1;
        // stage h_{t-1}: our 32-batch half, all 512 k
        {
            const float* src = g_hbuf[cur];
            #pragma unroll
            for (int i = 0; i < 8; i++) {
                int idx = tid + i*RT;
                int k = idx >> 3, q = idx & 7;
                *(float4*)&hs[k*SROW + q*4] = *(const float4*)&src[k*64 + hb*32 + q*4];
            }
        }
        // prefetch Gin into registers (hidden behind GEMM)
        float gin0 = g_Gin[(t*BATCH + hb*32 + 2*r_bp    )*G4 + r_jg];
        float gin1 = g_Gin[(t*BATCH + hb*32 + 2*r_bp + 1)*G4 + r_jg];
        __syncthreads();

        // GEMM: thread = (ks, cq, bq); 4 cols x 8 batches over 32 k
        ull acc[16];
        #pragma unroll
        for (int p = 0; p < 16; p++) acc[p] = 0ull;
        {
            const float* hbase = hs + bq*8;
            const float* wbase = ws + cq*4;
            #pragma unroll
            for (int kk = 0; kk < 32; kk++) {
                int k = ks*32 + kk;
                ulonglong2 ha = *(const ulonglong2*)(hbase + k*SROW);
                ulonglong2 hc = *(const ulonglong2*)(hbase + k*SROW + 4);
                float4 wv = *(const float4*)(wbase + k*SROW);
                ull w0 = fdup(wv.x), w1 = fdup(wv.y), w2 = fdup(wv.z), w3 = fdup(wv.w);
                acc[0]  = ffma2(ha.x, w0, acc[0]);
                acc[1]  = ffma2(ha.y, w0, acc[1]);
                acc[2]  = ffma2(hc.x, w0, acc[2]);
                acc[3]  = ffma2(hc.y, w0, acc[3]);
                acc[4]  = ffma2(ha.x, w1, acc[4]);
                acc[5]  = ffma2(ha.y, w1, acc[5]);
                acc[6]  = ffma2(hc.x, w1, acc[6]);
                acc[7]  = ffma2(hc.y, w1, acc[7]);
                acc[8]  = ffma2(ha.x, w2, acc[8]);
                acc[9]  = ffma2(ha.y, w2, acc[9]);
                acc[10] = ffma2(hc.x, w2, acc[10]);
                acc[11] = ffma2(hc.y, w2, acc[11]);
                acc[12] = ffma2(ha.x, w3, acc[12]);
                acc[13] = ffma2(ha.y, w3, acc[13]);
                acc[14] = ffma2(hc.x, w3, acc[14]);
                acc[15] = ffma2(hc.y, w3, acc[15]);
            }
        }
        #pragma unroll
        for (int c = 0; c < 4; c++)
            #pragma unroll
            for (int bp = 0; bp < 4; bp++)
                pt[ks*513 + (c*4+bp)*32 + lane] = acc[c*4 + bp];
        __syncthreads();

        // reduce 16 k-slices (4 ILP chains) + prefetched Gin
        {
            ull s0 = 0ull, s1 = 0ull, s2 = 0ull, s3 = 0ull;
            #pragma unroll
            for (int s = 0; s < 4; s++) {
                s0 = fadd2(s0, pt[(s   )*513 + tid]);
                s1 = fadd2(s1, pt[(s+4 )*513 + tid]);
                s2 = fadd2(s2, pt[(s+8 )*513 + tid]);
                s3 = fadd2(s3, pt[(s+12)*513 + tid]);
            }
            float2 gv = unpk(fadd2(fadd2(s0, s1), fadd2(s2, s3)));
            gv.x += gin0;
            gv.y += gin1;
            gb[(2*r_bp    )*33 + r_col] = gv.x;
            gb[(2*r_bp + 1)*33 + r_col] = gv.y;
        }
        __syncthreads();

        // activation
        if (tid < 256) {
            float xi = gb[ab*33 +      acc_];
            float xf = gb[ab*33 +  8 + acc_];
            float xg = gb[ab*33 + 16 + acc_];
            float xo = gb[ab*33 + 24 + acc_];
            float ig = 1.f/(1.f + __expf(-xi));
            float fg = 1.f/(1.f + __expf(-xf));
            float gg = tanhf(xg);
            float og = 1.f/(1.f + __expf(-xo));
            float cold = cs[tid];
            float hold = hs[ahg*SROW + ab];
            float cnew = fg*cold + ig*gg;
            float hnew = og * tanhf(cnew);
            int rb = t*BATCH + abg;
            g_hh[rb*HSZ + ahg] = hold;
            g_f [rb*HSZ + ahg] = fg;
            int dbase = rb*G3 + ahg;
            g_d[dbase]         = gg*ig*(1.f - ig);
            g_d[dbase + HSZ]   = cold*fg*(1.f - fg);
            g_d[dbase + 2*HSZ] = ig*(1.f - gg*gg);
            out[t*BATCH*HSZ + abg*HSZ + ahg] = hnew;
            cs[tid] = cnew;
            g_hbuf[1-cur][ahg*64 + abg] = hnew;
            Facc *= fg;
            if ((t % CLEN) == CLEN-1) {
                g_Fc[t/CLEN][abg*HSZ + ahg] = Facc;
                Facc = 1.f;
            }
            if (t == T_STEPS-1) out[OUT_CX + abg*HSZ + ahg] = cnew;
        }
        if (t < T_STEPS-1) grid_sync_flags(n, t);
    }
}

// ---------------------------------------------------------------------------
__global__ __launch_bounds__(256) void scanB_kernel() {
    int gid = blockIdx.x * blockDim.x + threadIdx.x;
    int c = gid >> 15, r = gid & 32767;
    int b = r >> 9, h = r & 511;
    float Q = 1.f;
    for (int c2 = c+1; c2 < NCHUNK; c2++) Q *= g_Fc[c2][b*HSZ + h];
    float F = Q, si = 0.f, sf = 0.f, sg = 0.f;
    #pragma unroll 5
    for (int t = c*CLEN + CLEN-1; t >= c*CLEN; t--) {
        int rb = t*BATCH + b;
        float fv = g_f[rb*HSZ + h];
        int dbase = rb*G3 + h;
        float di = g_d[dbase]         * F;
        float df = g_d[dbase + HSZ]   * F;
        float dg = g_d[dbase + 2*HSZ] * F;
        g_d[dbase]         = di;
        g_d[dbase + HSZ]   = df;
        g_d[dbase + 2*HSZ] = dg;
        si += di; sf += df; sg += dg;
        F *= fv;
    }
    g_ps[c][b*G3 + h]         = si;
    g_ps[c][b*G3 + HSZ + h]   = sf;
    g_ps[c][b*G3 + 2*HSZ + h] = sg;
}

__global__ __launch_bounds__(256) void scanC_kernel(float* __restrict__ out) {
    int gid = blockIdx.x * blockDim.x + threadIdx.x;
    float s = g_ps[0][gid] + g_ps[1][gid] + g_ps[2][gid] + g_ps[3][gid];
    out[OUT_EVB + gid] = s;
}

// ---------------------------------------------------------------------------
// Trace GEMM: ev[b][j][k] = sum_t a[t][b][j] * U[t][b][k].
// 512 threads, 128(j) x 256(k) tile, 8x8/thread, T chunks of 25.
template<int UD>
__global__ __launch_bounds__(512) void trace_kernel(const float* __restrict__ Uext,
                                                    float* __restrict__ out) {
    __shared__ float As[25][136];
    __shared__ float Us[25][264];
    const float* U = (UD == HSZ) ? (const float*)g_hh : Uext;
    const int b = blockIdx.z, j0 = blockIdx.y*128, k0 = blockIdx.x*256;
    const int tx = threadIdx.x & 31, ty = threadIdx.x >> 5;   // tx: 32 k-groups, ty: 16 j-groups
    ull acc[4][8] = {};
    for (int t0 = 0; t0 < T_STEPS; t0 += 25) {
        for (int idx = threadIdx.x; idx < 2400; idx += 512) {
            if (idx < 800) {
                int tt = idx >> 5, q = idx & 31;
                int rb = (t0+tt)*BATCH + b;
                *(float4*)&As[tt][q*4] = *(const float4*)&g_d[rb*G3 + j0 + q*4];
            } else {
                int e = idx - 800;
                int tt = e >> 6, q = e & 63;
                int rb = (t0+tt)*BATCH + b;
                *(float4*)&Us[tt][q*4] = *(const float4*)&U[rb*UD + k0 + q*4];
            }
        }
        __syncthreads();
        #pragma unroll
        for (int tt = 0; tt < 25; tt++) {
            ulonglong2 a01 = *(const ulonglong2*)&As[tt][ty*8];
            ulonglong2 a23 = *(const ulonglong2*)&As[tt][ty*8+4];
            float4 u0 = *(const float4*)&Us[tt][tx*8];
            float4 u1 = *(const float4*)&Us[tt][tx*8+4];
            ull ud[8];
            ud[0]=fdup(u0.x); ud[1]=fdup(u0.y); ud[2]=fdup(u0.z); ud[3]=fdup(u0.w);
            ud[4]=fdup(u1.x); ud[5]=fdup(u1.y); ud[6]=fdup(u1.z); ud[7]=fdup(u1.w);
            #pragma unroll
            for (int k = 0; k < 8; k++) {
                acc[0][k] = ffma2(a01.x, ud[k], acc[0][k]);
                acc[1][k] = ffma2(a01.y, ud[k], acc[1][k]);
                acc[2][k] = ffma2(a23.x, ud[k], acc[2][k]);
                acc[3][k] = ffma2(a23.y, ud[k], acc[3][k]);
            }
        }
        __syncthreads();
    }
    size_t base = (size_t)b * G3 * UD;
    #pragma unroll
    for (int jp = 0; jp < 4; jp++) {
        float2 p[8];
        #pragma unroll
        for (int k = 0; k < 8; k++) p[k] = unpk(acc[jp][k]);
        float* d0 = &out[base + (size_t)(j0 + ty*8 + 2*jp)*UD + k0 + tx*8];
        float* d1 = &out[base + (size_t)(j0 + ty*8 + 2*jp + 1)*UD + k0 + tx*8];
        *(float4*)d0       = make_float4(p[0].x, p[1].x, p[2].x, p[3].x);
        *(float4*)(d0 + 4) = make_float4(p[4].x, p[5].x, p[6].x, p[7].x);
        *(float4*)d1       = make_float4(p[0].y, p[1].y, p[2].y, p[3].y);
        *(float4*)(d1 + 4) = make_float4(p[4].y, p[5].y, p[6].y, p[7].y);
    }
}

// ---------------------------------------------------------------------------
extern "C" void kernel_launch(void* const* d_in, const int* in_sizes, int n_in,
                              void* d_out, int out_size) {
    const float* input = (const float*)d_in[0];
    const float* h0    = (const float*)d_in[1];
    const float* c0    = (const float*)d_in[2];
    const float* Wih   = (const float*)d_in[3];
    const float* Whh   = (const float*)d_in[4];
    const float* bih   = (const float*)d_in[5];
    const float* bhh   = (const float*)d_in[6];
    float* out = (float*)d_out;

    cudaFuncSetAttribute(recur_kernel, cudaFuncAttributeMaxDynamicSharedMemorySize, REC_SMEM_BYTES);

    prep_kernel<<<128, 256>>>(bih, bhh, h0);                                     // 0
    gin_kernel<<<dim3(G4/128, (T_STEPS*BATCH)/128), 256>>>(input, Wih);          // 1
    dummy_kernel<<<1, 32>>>();                                                   // 2
    recur_kernel<<<NB_REC, RT, REC_SMEM_BYTES>>>(Whh, c0, out);                  // 3 (profiled)
    scanB_kernel<<<NCHUNK*32768/256, 256>>>();                                   // 4
    scanC_kernel<<<BATCH*G3/256, 256>>>(out);                                    // 5
    trace_kernel<ISZ><<<dim3(ISZ/256, G3/128, BATCH), 512>>>(input, out + OUT_EVIH);
    trace_kernel<HSZ><<<dim3(HSZ/256, G3/128, BATCH), 512>>>(input, out + OUT_EVHH);
}

// round 8
// speedup vs baseline: 2.0103x; 2.0103x over previous
#include <cuda_runtime.h>
#include <math.h>

// Problem constants
#define T_STEPS 100
#define BATCH   64
#define ISZ     256
#define HSZ     512
#define G4      2048   // 4H
#define G3      1536   // 3H
#define NCHUNK  4
#define CLEN    25

// Output layout: outputs[T,B,H], cx[B,H], ev_ih[B,3H,I], ev_hh[B,3H,H], ev_b[B,3H,1]
#define OUT_CX   (T_STEPS*BATCH*HSZ)
#define OUT_EVIH (OUT_CX + BATCH*HSZ)
#define OUT_EVHH (OUT_EVIH + BATCH*G3*ISZ)
#define OUT_EVB  (OUT_EVHH + BATCH*G3*HSZ)

typedef unsigned long long ull;

// Device scratch
__device__ float g_bias[G4];
__device__ float g_Gin[T_STEPS*BATCH*G4];
__device__ float g_hh[T_STEPS*BATCH*HSZ];
__device__ float g_d[T_STEPS*BATCH*G3];
__device__ float g_f[T_STEPS*BATCH*HSZ];
__device__ float g_hbuf[2][HSZ*BATCH];             // k-major: [h][b]
__device__ float g_Fc[NCHUNK][BATCH*HSZ];
__device__ float g_ps[NCHUNK][BATCH*G3];
__device__ unsigned g_cnt2[64];                    // [0] even-half, [32] odd-half

// ---- f32x2 packed helpers -------------------------------------------------
__device__ __forceinline__ ull ffma2(ull a, ull b, ull c) {
    ull d; asm("fma.rn.f32x2 %0, %1, %2, %3;" : "=l"(d) : "l"(a), "l"(b), "l"(c)); return d;
}
__device__ __forceinline__ ull fadd2(ull a, ull b) {
    ull d; asm("add.rn.f32x2 %0, %1, %2;" : "=l"(d) : "l"(a), "l"(b)); return d;
}
__device__ __forceinline__ ull fdup(float x) {
    ull d; asm("mov.b64 %0, {%1, %1};" : "=l"(d) : "f"(x)); return d;
}
__device__ __forceinline__ float2 unpk(ull v) {
    float2 r; asm("mov.b64 {%0, %1}, %2;" : "=f"(r.x), "=f"(r.y) : "l"(v)); return r;
}

// ---------------------------------------------------------------------------
__global__ void prep_kernel(const float* __restrict__ bih, const float* __restrict__ bhh,
                            const float* __restrict__ h0) {
    int gid = blockIdx.x * blockDim.x + threadIdx.x;
    if (gid < 64) g_cnt2[gid] = 0u;
    if (gid < G4) g_bias[gid] = bih[gid] + bhh[gid];
    if (gid < BATCH*HSZ) {
        int k = gid >> 6, b = gid & 63;
        g_hbuf[0][gid] = h0[b*HSZ + k];     // k-major
    }
}

__global__ void dummy_kernel() {}

// ---------------------------------------------------------------------------
// Gin[r][j] = sum_i X[r][i]*W_ih[j][i] + bias[j].  128x128 tile, 8x8/thread.
__global__ __launch_bounds__(256) void gin_kernel(const float* __restrict__ X,
                                                  const float* __restrict__ Wih) {
    __shared__ float As[32][136];
    __shared__ float Bs[32][136];
    const int j0 = blockIdx.x * 128;
    const int r0 = blockIdx.y * 128;
    const int tx = threadIdx.x & 15, ty = threadIdx.x >> 4;
    ull acc[8][4] = {};
    for (int k0 = 0; k0 < ISZ; k0 += 32) {
        for (int idx = threadIdx.x; idx < 128*8; idx += 256) {
            int rr = idx >> 3, kq = idx & 7;
            float4 v = *(const float4*)&X[(r0+rr)*ISZ + k0 + kq*4];
            As[kq*4+0][rr] = v.x; As[kq*4+1][rr] = v.y;
            As[kq*4+2][rr] = v.z; As[kq*4+3][rr] = v.w;
        }
        for (int idx = threadIdx.x; idx < 128*8; idx += 256) {
            int jj = idx >> 3, kq = idx & 7;
            float4 v = *(const float4*)&Wih[(j0+jj)*ISZ + k0 + kq*4];
            Bs[kq*4+0][jj] = v.x; Bs[kq*4+1][jj] = v.y;
            Bs[kq*4+2][jj] = v.z; Bs[kq*4+3][jj] = v.w;
        }
        __syncthreads();
        #pragma unroll
        for (int kk = 0; kk < 32; kk++) {
            float4 a0 = *(const float4*)&As[kk][ty*8];
            float4 a1 = *(const float4*)&As[kk][ty*8+4];
            ulonglong2 bv0 = *(const ulonglong2*)&Bs[kk][tx*8];
            ulonglong2 bv1 = *(const ulonglong2*)&Bs[kk][tx*8+4];
            ull ad[8];
            ad[0]=fdup(a0.x); ad[1]=fdup(a0.y); ad[2]=fdup(a0.z); ad[3]=fdup(a0.w);
            ad[4]=fdup(a1.x); ad[5]=fdup(a1.y); ad[6]=fdup(a1.z); ad[7]=fdup(a1.w);
            #pragma unroll
            for (int r = 0; r < 8; r++) {
                acc[r][0] = ffma2(ad[r], bv0.x, acc[r][0]);
                acc[r][1] = ffma2(ad[r], bv0.y, acc[r][1]);
                acc[r][2] = ffma2(ad[r], bv1.x, acc[r][2]);
                acc[r][3] = ffma2(ad[r], bv1.y, acc[r][3]);
            }
        }
        __syncthreads();
    }
    float4 b0 = *(const float4*)&g_bias[j0 + tx*8];
    float4 b1 = *(const float4*)&g_bias[j0 + tx*8 + 4];
    #pragma unroll
    for (int r = 0; r < 8; r++) {
        float2 p0 = unpk(acc[r][0]), p1 = unpk(acc[r][1]);
        float2 p2 = unpk(acc[r][2]), p3 = unpk(acc[r][3]);
        float* dst = &g_Gin[(r0+ty*8+r)*G4 + j0 + tx*8];
        *(float4*)dst       = make_float4(p0.x+b0.x, p0.y+b0.y, p1.x+b0.z, p1.y+b0.w);
        *(float4*)(dst + 4) = make_float4(p2.x+b1.x, p2.y+b1.y, p3.x+b1.z, p3.y+b1.w);
    }
}

// ---------------------------------------------------------------------------
// Persistent recurrence: 128 CTAs x 512 threads.
// CTA n: batch-half hb=n&1 (32 b), cell-group cg=n>>1 (8 cells -> 32 gate-cols).
// Even/odd batch halves are fully independent -> split 64-CTA barriers.
#define NB_REC 128
#define RT     512
#define SROW   36

// smem float offsets
#define OFF_WS 0
#define OFF_HS (512*SROW)                 // 18432
#define OFF_PT (2*512*SROW)               // 36864 (ull: 16*513)
#define OFF_GB (OFF_PT + 16*513*2)        // 53280
#define OFF_CS (OFF_GB + 32*33)           // 54336
#define REC_SMEM_FLOATS (OFF_CS + 256)    // 54592
#define REC_SMEM_BYTES  (REC_SMEM_FLOATS*4)

// Half-grid barrier: 64 CTAs per batch-half, monotonic atomic counter.
__device__ __forceinline__ void grid_sync_half(int hb, int t) {
    __syncthreads();
    if (threadIdx.x == 0) {
        __threadfence();
        atomicAdd(&g_cnt2[hb*32], 1u);
        unsigned target = (unsigned)(t + 1) * 64u;
        while (*(volatile unsigned*)&g_cnt2[hb*32] < target) {}
        __threadfence();
    }
    __syncthreads();
}

__global__ __launch_bounds__(RT) void recur_kernel(const float* __restrict__ Whh,
                                                   const float* __restrict__ c0,
                                                   float* __restrict__ out) {
    extern __shared__ float sm[];
    float* ws = sm + OFF_WS;          // [512][SROW] ws[k][c]
    float* hs = sm + OFF_HS;          // [512][SROW] hs[k][b]
    ull*   pt = (ull*)(sm + OFF_PT);  // [16][513]
    float* gb = sm + OFF_GB;          // [32][33] final gates
    float* cs = sm + OFF_CS;          // [256]

    const int tid = threadIdx.x;
    const int n   = blockIdx.x;
    const int hb  = n & 1, cg = n >> 1;
    // GEMM mapping
    const int ks = tid >> 5, lane = tid & 31;
    const int cq = lane >> 2, bq = lane & 3;
    // reduce mapping
    const int r_l = tid & 31, r_i = tid >> 5;
    const int r_col = ((r_l >> 2) << 2) + (r_i >> 2);
    const int r_bp  = ((r_l & 3) << 2) + (r_i & 3);
    const int r_jg  = ((r_col >> 3) * HSZ) + cg*8 + (r_col & 7);
    // activation mapping (tid < 256)
    const int ab = tid >> 3, acc_ = tid & 7;
    const int ahg = cg*8 + acc_;
    const int abg = hb*32 + ab;

    // one-time: weights transposed ws[k][c], c-state
    for (int idx = tid; idx < 32*512; idx += RT) {
        int c = idx >> 9, k = idx & 511;
        int jg = ((c >> 3) * HSZ) + cg*8 + (c & 7);
        ws[k*SROW + c] = Whh[jg*HSZ + k];
    }
    if (tid < 256) cs[tid] = c0[abg*HSZ + ahg];
    float Facc = 1.f;
    __syncthreads();

    for (int t = 0; t < T_STEPS; t++) {
        const int cur = t & 1;
        // per-warp stage: warp ks stages ONLY its own 32 hs rows (k in [32ks,32ks+32))
        {
            const float* src = g_hbuf[cur];
            const int kr0 = ks*32;
            #pragma unroll
            for (int i = 0; i < 8; i++) {
                int idx = lane + i*32;                 // 0..255
                int kr = kr0 + (idx >> 3), q = idx & 7;
                *(float4*)&hs[kr*SROW + q*4] = *(const float4*)&src[kr*64 + hb*32 + q*4];
            }
        }
        // prefetch Gin into registers (hidden behind GEMM)
        float gin0 = g_Gin[(t*BATCH + hb*32 + 2*r_bp    )*G4 + r_jg];
        float gin1 = g_Gin[(t*BATCH + hb*32 + 2*r_bp + 1)*G4 + r_jg];
        __syncwarp();

        // GEMM: thread = (ks, cq, bq); 4 cols x 8 batches over 32 k (own rows only)
        ull acc[16];
        #pragma unroll
        for (int p = 0; p < 16; p++) acc[p] = 0ull;
        {
            const float* hbase = hs + bq*8;
            const float* wbase = ws + cq*4;
            #pragma unroll
            for (int kk = 0; kk < 32; kk++) {
                int k = ks*32 + kk;
                ulonglong2 ha = *(const ulonglong2*)(hbase + k*SROW);
                ulonglong2 hc = *(const ulonglong2*)(hbase + k*SROW + 4);
                float4 wv = *(const float4*)(wbase + k*SROW);
                ull w0 = fdup(wv.x), w1 = fdup(wv.y), w2 = fdup(wv.z), w3 = fdup(wv.w);
                acc[0]  = ffma2(ha.x, w0, acc[0]);
                acc[1]  = ffma2(ha.y, w0, acc[1]);
                acc[2]  = ffma2(hc.x, w0, acc[2]);
                acc[3]  = ffma2(hc.y, w0, acc[3]);
                acc[4]  = ffma2(ha.x, w1, acc[4]);
                acc[5]  = ffma2(ha.y, w1, acc[5]);
                acc[6]  = ffma2(hc.x, w1, acc[6]);
                acc[7]  = ffma2(hc.y, w1, acc[7]);
                acc[8]  = ffma2(ha.x, w2, acc[8]);
                acc[9]  = ffma2(ha.y, w2, acc[9]);
                acc[10] = ffma2(hc.x, w2, acc[10]);
                acc[11] = ffma2(hc.y, w2, acc[11]);
                acc[12] = ffma2(ha.x, w3, acc[12]);
                acc[13] = ffma2(ha.y, w3, acc[13]);
                acc[14] = ffma2(hc.x, w3, acc[14]);
                acc[15] = ffma2(hc.y, w3, acc[15]);
            }
        }
        #pragma unroll
        for (int c = 0; c < 4; c++)
            #pragma unroll
            for (int bp = 0; bp < 4; bp++)
                pt[ks*513 + (c*4+bp)*32 + lane] = acc[c*4 + bp];
        __syncthreads();

        // reduce 16 k-slices (4 ILP chains) + prefetched Gin
        {
            ull s0 = 0ull, s1 = 0ull, s2 = 0ull, s3 = 0ull;
            #pragma unroll
            for (int s = 0; s < 4; s++) {
                s0 = fadd2(s0, pt[(s   )*513 + tid]);
                s1 = fadd2(s1, pt[(s+4 )*513 + tid]);
                s2 = fadd2(s2, pt[(s+8 )*513 + tid]);
                s3 = fadd2(s3, pt[(s+12)*513 + tid]);
            }
            float2 gv = unpk(fadd2(fadd2(s0, s1), fadd2(s2, s3)));
            gv.x += gin0;
            gv.y += gin1;
            gb[(2*r_bp    )*33 + r_col] = gv.x;
            gb[(2*r_bp + 1)*33 + r_col] = gv.y;
        }
        __syncthreads();

        // activation
        if (tid < 256) {
            float xi = gb[ab*33 +      acc_];
            float xf = gb[ab*33 +  8 + acc_];
            float xg = gb[ab*33 + 16 + acc_];
            float xo = gb[ab*33 + 24 + acc_];
            float ig = 1.f/(1.f + __expf(-xi));
            float fg = 1.f/(1.f + __expf(-xf));
            float gg = tanhf(xg);
            float og = 1.f/(1.f + __expf(-xo));
            float cold = cs[tid];
            float hold = hs[ahg*SROW + ab];
            float cnew = fg*cold + ig*gg;
            float hnew = og * tanhf(cnew);
            int rb = t*BATCH + abg;
            g_hh[rb*HSZ + ahg] = hold;
            g_f [rb*HSZ + ahg] = fg;
            int dbase = rb*G3 + ahg;
            g_d[dbase]         = gg*ig*(1.f - ig);
            g_d[dbase + HSZ]   = cold*fg*(1.f - fg);
            g_d[dbase + 2*HSZ] = ig*(1.f - gg*gg);
            out[t*BATCH*HSZ + abg*HSZ + ahg] = hnew;
            cs[tid] = cnew;
            g_hbuf[1-cur][ahg*64 + abg] = hnew;
            Facc *= fg;
            if ((t % CLEN) == CLEN-1) {
                g_Fc[t/CLEN][abg*HSZ + ahg] = Facc;
                Facc = 1.f;
            }
            if (t == T_STEPS-1) out[OUT_CX + abg*HSZ + ahg] = cnew;
        }
        if (t < T_STEPS-1) grid_sync_half(hb, t);
    }
}

// ---------------------------------------------------------------------------
__global__ __launch_bounds__(256) void scanB_kernel() {
    int gid = blockIdx.x * blockDim.x + threadIdx.x;
    int c = gid >> 15, r = gid & 32767;
    int b = r >> 9, h = r & 511;
    float Q = 1.f;
    for (int c2 = c+1; c2 < NCHUNK; c2++) Q *= g_Fc[c2][b*HSZ + h];
    float F = Q, si = 0.f, sf = 0.f, sg = 0.f;
    #pragma unroll 5
    for (int t = c*CLEN + CLEN-1; t >= c*CLEN; t--) {
        int rb = t*BATCH + b;
        float fv = g_f[rb*HSZ + h];
        int dbase = rb*G3 + h;
        float di = g_d[dbase]         * F;
        float df = g_d[dbase + HSZ]   * F;
        float dg = g_d[dbase + 2*HSZ] * F;
        g_d[dbase]         = di;
        g_d[dbase + HSZ]   = df;
        g_d[dbase + 2*HSZ] = dg;
        si += di; sf += df; sg += dg;
        F *= fv;
    }
    g_ps[c][b*G3 + h]         = si;
    g_ps[c][b*G3 + HSZ + h]   = sf;
    g_ps[c][b*G3 + 2*HSZ + h] = sg;
}

__global__ __launch_bounds__(256) void scanC_kernel(float* __restrict__ out) {
    int gid = blockIdx.x * blockDim.x + threadIdx.x;
    float s = g_ps[0][gid] + g_ps[1][gid] + g_ps[2][gid] + g_ps[3][gid];
    out[OUT_EVB + gid] = s;
}

// ---------------------------------------------------------------------------
// Trace GEMM: ev[b][j][k] = sum_t a[t][b][j] * U[t][b][k]. 128x128, 8x8/thread.
template<int UD>
__global__ __launch_bounds__(256) void trace_kernel(const float* __restrict__ Uext,
                                                    float* __restrict__ out) {
    __shared__ float As[25][136];
    __shared__ float Us[25][136];
    const float* U = (UD == HSZ) ? (const float*)g_hh : Uext;
    const int b = blockIdx.z, j0 = blockIdx.y*128, k0 = blockIdx.x*128;
    const int tx = threadIdx.x & 15, ty = threadIdx.x >> 4;
    ull acc[4][8] = {};
    for (int t0 = 0; t0 < T_STEPS; t0 += 25) {
        for (int idx = threadIdx.x; idx < 25*32*2; idx += 256) {
            int which = idx >= 800;
            int i2 = which ? idx - 800 : idx;
            int tt = i2 >> 5, q = i2 & 31;
            int rb = (t0+tt)*BATCH + b;
            if (!which) *(float4*)&As[tt][q*4] = *(const float4*)&g_d[rb*G3 + j0 + q*4];
            else        *(float4*)&Us[tt][q*4] = *(const float4*)&U[rb*UD + k0 + q*4];
        }
        __syncthreads();
        #pragma unroll
        for (int tt = 0; tt < 25; tt++) {
            ulonglong2 a01 = *(const ulonglong2*)&As[tt][ty*8];
            ulonglong2 a23 = *(const ulonglong2*)&As[tt][ty*8+4];
            float4 u0 = *(const float4*)&Us[tt][tx*8];
            float4 u1 = *(const float4*)&Us[tt][tx*8+4];
            ull ud[8];
            ud[0]=fdup(u0.x); ud[1]=fdup(u0.y); ud[2]=fdup(u0.z); ud[3]=fdup(u0.w);
            ud[4]=fdup(u1.x); ud[5]=fdup(u1.y); ud[6]=fdup(u1.z); ud[7]=fdup(u1.w);
            #pragma unroll
            for (int k = 0; k < 8; k++) {
                acc[0][k] = ffma2(a01.x, ud[k], acc[0][k]);
                acc[1][k] = ffma2(a01.y, ud[k], acc[1][k]);
                acc[2][k] = ffma2(a23.x, ud[k], acc[2][k]);
                acc[3][k] = ffma2(a23.y, ud[k], acc[3][k]);
            }
        }
        __syncthreads();
    }
    size_t base = (size_t)b * G3 * UD;
    #pragma unroll
    for (int jp = 0; jp < 4; jp++) {
        float2 p[8];
        #pragma unroll
        for (int k = 0; k < 8; k++) p[k] = unpk(acc[jp][k]);
        float* d0 = &out[base + (size_t)(j0 + ty*8 + 2*jp)*UD + k0 + tx*8];
        float* d1 = &out[base + (size_t)(j0 + ty*8 + 2*jp + 1)*UD + k0 + tx*8];
        *(float4*)d0       = make_float4(p[0].x, p[1].x, p[2].x, p[3].x);
        *(float4*)(d0 + 4) = make_float4(p[4].x, p[5].x, p[6].x, p[7].x);
        *(float4*)d1       = make_float4(p[0].y, p[1].y, p[2].y, p[3].y);
        *(float4*)(d1 + 4) = make_float4(p[4].y, p[5].y, p[6].y, p[7].y);
    }
}

// ---------------------------------------------------------------------------
extern "C" void kernel_launch(void* const* d_in, const int* in_sizes, int n_in,
                              void* d_out, int out_size) {
    const float* input = (const float*)d_in[0];
    const float* h0    = (const float*)d_in[1];
    const float* c0    = (const float*)d_in[2];
    const float* Wih   = (const float*)d_in[3];
    const float* Whh   = (const float*)d_in[4];
    const float* bih   = (const float*)d_in[5];
    const float* bhh   = (const float*)d_in[6];
    float* out = (float*)d_out;

    cudaFuncSetAttribute(recur_kernel, cudaFuncAttributeMaxDynamicSharedMemorySize, REC_SMEM_BYTES);

    prep_kernel<<<128, 256>>>(bih, bhh, h0);                                     // 0
    gin_kernel<<<dim3(G4/128, (T_STEPS*BATCH)/128), 256>>>(input, Wih);          // 1
    dummy_kernel<<<1, 32>>>();                                                   // 2
    recur_kernel<<<NB_REC, RT, REC_SMEM_BYTES>>>(Whh, c0, out);                  // 3 (profiled)
    scanB_kernel<<<NCHUNK*32768/256, 256>>>();                                   // 4
    scanC_kernel<<<BATCH*G3/256, 256>>>(out);                                    // 5
    trace_kernel<ISZ><<<dim3(ISZ/128, G3/128, BATCH), 256>>>(input, out + OUT_EVIH);
    trace_kernel<HSZ><<<dim3(HSZ/128, G3/128, BATCH), 256>>>(input, out + OUT_EVHH);
}